// round 9
// baseline (speedup 1.0000x reference)
#include <cuda_runtime.h>
#include <cuda_fp16.h>
#include <math.h>
#include <stdint.h>

#define N_NODES 65536
#define EMBED 512
#define FFDIM 2048
#define QKVDIM 1536
#define NHEADS 8
#define HDIM 64

// ---------------- scratch ----------------------------------------------------
__device__ __half g_h[(size_t)N_NODES * EMBED];
__device__ __half g_qkv[(size_t)N_NODES * QKVDIM];
__device__ __half g_attnh[(size_t)N_NODES * EMBED];
__device__ __half g_x1h[(size_t)N_NODES * EMBED];
__device__ __half g_ffh[(size_t)N_NODES * FFDIM];
__device__ __half g_wqkv[QKVDIM * EMBED];
__device__ float  g_bqkv[QKVDIM];
__device__ __half g_wo[EMBED * EMBED];
__device__ __half g_w1[FFDIM * EMBED];
__device__ __half g_w2[EMBED * FFDIM];

// ---------------- ptx helpers ------------------------------------------------
__device__ __forceinline__ uint32_t smem_u32(const void* p) {
    uint32_t a;
    asm("{ .reg .u64 t; cvta.to.shared.u64 t, %1; cvt.u32.u64 %0, t; }" : "=r"(a) : "l"(p));
    return a;
}
__device__ __forceinline__ void cp_async16(uint32_t saddr, const void* gaddr) {
    asm volatile("cp.async.cg.shared.global [%0], [%1], 16;\n" :: "r"(saddr), "l"(gaddr));
}
__device__ __forceinline__ void cpasync_mbar_arrive(uint32_t mbar) {
    asm volatile("cp.async.mbarrier.arrive.noinc.shared.b64 [%0];" :: "r"(mbar) : "memory");
}
__device__ __forceinline__ void mbar_init(uint32_t mbar, uint32_t cnt) {
    asm volatile("mbarrier.init.shared.b64 [%0], %1;" :: "r"(mbar), "r"(cnt) : "memory");
}
__device__ __forceinline__ void mbar_arrive(uint32_t mbar) {
    asm volatile("mbarrier.arrive.shared.b64 _, [%0];" :: "r"(mbar) : "memory");
}
__device__ __forceinline__ void mbar_wait(uint32_t mbar, uint32_t parity) {
    asm volatile(
        "{\n\t.reg .pred P;\n\t"
        "WL%=:\n\t"
        "mbarrier.try_wait.parity.acquire.cta.shared::cta.b64 P, [%0], %1, 0x989680;\n\t"
        "@P bra WD%=;\n\t"
        "bra WL%=;\n\t"
        "WD%=:\n\t}"
        :: "r"(mbar), "r"(parity) : "memory");
}
__device__ __forceinline__ void ldm_x4(uint32_t* r, uint32_t addr) {
    asm volatile("ldmatrix.sync.aligned.m8n8.x4.shared.b16 {%0,%1,%2,%3}, [%4];"
                 : "=r"(r[0]), "=r"(r[1]), "=r"(r[2]), "=r"(r[3]) : "r"(addr));
}
__device__ __forceinline__ void mma16816(float* d, const uint32_t* a, const uint32_t* b) {
    asm volatile(
        "mma.sync.aligned.m16n8k16.row.col.f32.f16.f16.f32 "
        "{%0,%1,%2,%3}, {%4,%5,%6,%7}, {%8,%9}, {%0,%1,%2,%3};"
        : "+f"(d[0]), "+f"(d[1]), "+f"(d[2]), "+f"(d[3])
        : "r"(a[0]), "r"(a[1]), "r"(a[2]), "r"(a[3]), "r"(b[0]), "r"(b[1]));
}
__device__ __forceinline__ void mma16816h(uint32_t* d, const uint32_t* a, const uint32_t* b) {
    asm volatile(
        "mma.sync.aligned.m16n8k16.row.col.f16.f16.f16.f16 "
        "{%0,%1}, {%2,%3,%4,%5}, {%6,%7}, {%0,%1};"
        : "+r"(d[0]), "+r"(d[1])
        : "r"(a[0]), "r"(a[1]), "r"(a[2]), "r"(a[3]), "r"(b[0]), "r"(b[1]));
}

// ---------------- HMMA fp16 GEMM: C[N,M] = A[N,K] @ B[M,K]^T + epilogue -----
// CTA 128x128, BK=64 (ROWB=144 -> conflict-free ldmatrix), 3-stage cp.async
// pipeline synchronized by mbarriers (no per-chunk __syncthreads).
// 8 warps (4x2), warp tile 32x64.
// ACCHALF: accumulate in fp16 within each K=64 chunk (4 chained f16-acc MMAs,
// halved RF operand traffic), promote to persistent fp32 acc once per chunk.
#define BM 128
#define BN 128
#define BK 64
#define ROWB 144
#define TILEB (128 * ROWB)           // 18432 per tile (A or B)
#define STAGEB (2 * TILEB)           // 36864 per stage
#define GSMEM (64 + 3 * STAGEB)      // 110656

template<bool ACCHALF, bool RELU, bool HASRES, bool RESHALF, bool OUTHALF>
__global__ void __launch_bounds__(256, 2) gemm16_kernel(
    const __half* __restrict__ A, const __half* __restrict__ B,
    const float* __restrict__ bias, const void* __restrict__ resv,
    void* __restrict__ Cv, int K, int M)
{
    extern __shared__ __align__(16) char smem[];
    const uint32_t sb = smem_u32(smem);
    const uint32_t tb = sb + 64;     // tiles base
    const int tid = threadIdx.x;
    const int lane = tid & 31;
    const int wid = tid >> 5;
    const int wm = wid & 3;
    const int wn = wid >> 2;
    const int bm = blockIdx.y * BM;
    const int bn = blockIdx.x * BN;

    if (tid == 0) {
#pragma unroll
        for (int s = 0; s < 3; s++) {
            mbar_init(sb + s * 8, 256);        // full[s]
            mbar_init(sb + 24 + s * 8, 256);   // free[s]
        }
    }
    __syncthreads();

    // cp.async slots: tile = 128 rows x 8 segs(16B) = 1024 segs, 4/thread/tile
    uint32_t soff[4];
    const __half* agp[4];
    const __half* bgp[4];
#pragma unroll
    for (int i = 0; i < 4; i++) {
        int seg = tid + i * 256;
        int r = seg >> 3, c = seg & 7;
        soff[i] = r * ROWB + c * 16;
        agp[i] = A + (size_t)(bm + r) * K + c * 8;
        bgp[i] = B + (size_t)(bn + r) * K + c * 8;
    }

    uint32_t a_off[2], b_off[4];
#pragma unroll
    for (int mf = 0; mf < 2; mf++)
        a_off[mf] = (wm * 32 + mf * 16 + (lane & 15)) * ROWB + ((lane >> 4) * 16);
#pragma unroll
    for (int p = 0; p < 4; p++)
        b_off[p] = (wn * 64 + p * 16 + ((lane >> 4) << 3) + (lane & 7)) * ROWB
                 + (((lane >> 3) & 1) * 16);

    float acc[2][8][4];
#pragma unroll
    for (int i = 0; i < 2; i++)
#pragma unroll
        for (int j = 0; j < 8; j++)
#pragma unroll
            for (int t = 0; t < 4; t++) acc[i][j][t] = 0.f;

    const int NC = K >> 6;

    // prologue: prefetch chunks 0 and 1 (stages 0, 1)
#pragma unroll
    for (int pc = 0; pc < 2; pc++) {
        const uint32_t base = tb + pc * STAGEB;
        const int ko = pc * BK;
#pragma unroll
        for (int i = 0; i < 4; i++) {
            cp_async16(base + soff[i], agp[i] + ko);
            cp_async16(base + TILEB + soff[i], bgp[i] + ko);
        }
        cpasync_mbar_arrive(sb + pc * 8);   // full[pc]
    }

    int st = 0;            // compute stage
    uint32_t pful = 0;     // full-wait parity for compute
    int pt = 2;            // prefetch stage
    uint32_t wfree = 1;    // free-wait parity

#pragma unroll 1
    for (int chunk = 0; chunk < NC; chunk++) {
        // prefetch chunk+2 into stage pt
        const int pc = chunk + 2;
        if (pc < NC) {
            if (pc >= 3) mbar_wait(sb + 24 + pt * 8, wfree);
            const uint32_t base = tb + pt * STAGEB;
            const int ko = pc * BK;
#pragma unroll
            for (int i = 0; i < 4; i++) {
                cp_async16(base + soff[i], agp[i] + ko);
                cp_async16(base + TILEB + soff[i], bgp[i] + ko);
            }
            cpasync_mbar_arrive(sb + pt * 8);
            if (pt == 2) { pt = 0; wfree ^= 1u; } else pt++;
        }

        // consume stage st
        mbar_wait(sb + st * 8, pful);
        const uint32_t ab = tb + st * STAGEB;
        const uint32_t bb = ab + TILEB;

        if (ACCHALF) {
            uint32_t hacc[16][2];
#pragma unroll
            for (int t = 0; t < 16; t++) { hacc[t][0] = 0u; hacc[t][1] = 0u; }
#pragma unroll
            for (int ks = 0; ks < 4; ks++) {
                uint32_t afr[2][4], bfr[4][4];
                ldm_x4(afr[0], ab + a_off[0] + ks * 32);
                ldm_x4(afr[1], ab + a_off[1] + ks * 32);
#pragma unroll
                for (int p = 0; p < 4; p++) ldm_x4(bfr[p], bb + b_off[p] + ks * 32);
#pragma unroll
                for (int mf = 0; mf < 2; mf++)
#pragma unroll
                    for (int nf = 0; nf < 8; nf++)
                        mma16816h(hacc[mf * 8 + nf], afr[mf], &bfr[nf >> 1][(nf & 1) * 2]);
            }
            // promote fp16 chunk-partials into fp32 accumulators
#pragma unroll
            for (int mf = 0; mf < 2; mf++)
#pragma unroll
                for (int nf = 0; nf < 8; nf++) {
                    float2 lo = __half22float2(*(__half2*)&hacc[mf * 8 + nf][0]);
                    float2 hi = __half22float2(*(__half2*)&hacc[mf * 8 + nf][1]);
                    acc[mf][nf][0] += lo.x; acc[mf][nf][1] += lo.y;
                    acc[mf][nf][2] += hi.x; acc[mf][nf][3] += hi.y;
                }
        } else {
#pragma unroll
            for (int ks = 0; ks < 4; ks++) {
                uint32_t afr[2][4], bfr[4][4];
                ldm_x4(afr[0], ab + a_off[0] + ks * 32);
                ldm_x4(afr[1], ab + a_off[1] + ks * 32);
#pragma unroll
                for (int p = 0; p < 4; p++) ldm_x4(bfr[p], bb + b_off[p] + ks * 32);
#pragma unroll
                for (int mf = 0; mf < 2; mf++)
#pragma unroll
                    for (int nf = 0; nf < 8; nf++)
                        mma16816(acc[mf][nf], afr[mf], &bfr[nf >> 1][(nf & 1) * 2]);
            }
        }

        mbar_arrive(sb + 24 + st * 8);   // free[st]
        if (st == 2) { st = 0; pful ^= 1u; } else st++;
    }

    // epilogue
    const int mrow = bm + wm * 32 + (lane >> 2);
    const int ncol = bn + wn * 64 + (lane & 3) * 2;
#pragma unroll
    for (int mf = 0; mf < 2; mf++) {
#pragma unroll
        for (int half8 = 0; half8 < 2; half8++) {
            const int row = mrow + mf * 16 + half8 * 8;
#pragma unroll
            for (int nf = 0; nf < 8; nf++) {
                const int col = ncol + nf * 8;
                float c0 = acc[mf][nf][half8 * 2 + 0];
                float c1 = acc[mf][nf][half8 * 2 + 1];
                float2 b2 = *(const float2*)&bias[col];
                c0 += b2.x; c1 += b2.y;
                if (RELU) { c0 = fmaxf(c0, 0.f); c1 = fmaxf(c1, 0.f); }
                if (HASRES) {
                    if (RESHALF) {
                        __half2 r2 = *(const __half2*)((const __half*)resv + (size_t)row * M + col);
                        float2 rf = __half22float2(r2);
                        c0 += rf.x; c1 += rf.y;
                    } else {
                        float2 r2 = *(const float2*)((const float*)resv + (size_t)row * M + col);
                        c0 += r2.x; c1 += r2.y;
                    }
                }
                if (OUTHALF) {
                    *(__half2*)((__half*)Cv + (size_t)row * M + col) =
                        __floats2half2_rn(c0, c1);
                } else {
                    *(float2*)((float*)Cv + (size_t)row * M + col) =
                        make_float2(c0, c1);
                }
            }
        }
    }
}

// ---------------- LayerNorm (fp32 in) -> fp16 ---------------------------------
__global__ void __launch_bounds__(128) ln_kernel(
    const float* __restrict__ x, const float* __restrict__ gamma,
    const float* __restrict__ beta, __half* __restrict__ y)
{
    int row = blockIdx.x;
    int t = threadIdx.x;
    const float4* xp = (const float4*)(x + (size_t)row * EMBED);
    float4 v = xp[t];
    float s  = v.x + v.y + v.z + v.w;
    float s2 = v.x*v.x + v.y*v.y + v.z*v.z + v.w*v.w;
#pragma unroll
    for (int off = 16; off > 0; off >>= 1) {
        s  += __shfl_down_sync(0xffffffffu, s,  off);
        s2 += __shfl_down_sync(0xffffffffu, s2, off);
    }
    __shared__ float red[2][4];
    int warp = t >> 5, lane = t & 31;
    if (lane == 0) { red[0][warp] = s; red[1][warp] = s2; }
    __syncthreads();
    float tot  = red[0][0] + red[0][1] + red[0][2] + red[0][3];
    float tot2 = red[1][0] + red[1][1] + red[1][2] + red[1][3];
    float mu  = tot  * (1.0f / EMBED);
    float var = tot2 * (1.0f / EMBED) - mu * mu;
    float inv = rsqrtf(var + 1e-5f);
    float4 g4 = ((const float4*)gamma)[t];
    float4 b4 = ((const float4*)beta)[t];
    __half2* yp = (__half2*)(y + (size_t)row * EMBED) + t * 2;
    yp[0] = __floats2half2_rn((v.x - mu) * inv * g4.x + b4.x,
                              (v.y - mu) * inv * g4.y + b4.y);
    yp[1] = __floats2half2_rn((v.z - mu) * inv * g4.z + b4.z,
                              (v.w - mu) * inv * g4.w + b4.w);
}

// ---------------- LayerNorm (fp16 in) -> fp16 ---------------------------------
__global__ void __launch_bounds__(128) ln_h_kernel(
    const __half* __restrict__ x, const float* __restrict__ gamma,
    const float* __restrict__ beta, __half* __restrict__ y)
{
    int row = blockIdx.x;
    int t = threadIdx.x;
    uint2 raw = ((const uint2*)(x + (size_t)row * EMBED))[t];
    __half2 h0 = *reinterpret_cast<__half2*>(&raw.x);
    __half2 h1 = *reinterpret_cast<__half2*>(&raw.y);
    float2 f0 = __half22float2(h0);
    float2 f1 = __half22float2(h1);
    float s  = f0.x + f0.y + f1.x + f1.y;
    float s2 = f0.x*f0.x + f0.y*f0.y + f1.x*f1.x + f1.y*f1.y;
#pragma unroll
    for (int off = 16; off > 0; off >>= 1) {
        s  += __shfl_down_sync(0xffffffffu, s,  off);
        s2 += __shfl_down_sync(0xffffffffu, s2, off);
    }
    __shared__ float red[2][4];
    int warp = t >> 5, lane = t & 31;
    if (lane == 0) { red[0][warp] = s; red[1][warp] = s2; }
    __syncthreads();
    float tot  = red[0][0] + red[0][1] + red[0][2] + red[0][3];
    float tot2 = red[1][0] + red[1][1] + red[1][2] + red[1][3];
    float mu  = tot  * (1.0f / EMBED);
    float var = tot2 * (1.0f / EMBED) - mu * mu;
    float inv = rsqrtf(var + 1e-5f);
    float4 g4 = ((const float4*)gamma)[t];
    float4 b4 = ((const float4*)beta)[t];
    __half2* yp = (__half2*)(y + (size_t)row * EMBED) + t * 2;
    yp[0] = __floats2half2_rn((f0.x - mu) * inv * g4.x + b4.x,
                              (f0.y - mu) * inv * g4.y + b4.y);
    yp[1] = __floats2half2_rn((f1.x - mu) * inv * g4.z + b4.z,
                              (f1.y - mu) * inv * g4.w + b4.w);
}

// ---------------- per-node attention (8x8 heads), fp16 fused qkv -> fp16 -----
__global__ void __launch_bounds__(256) attn_kernel(
    const __half* __restrict__ qkv, __half* __restrict__ out)
{
    int slot = threadIdx.x >> 6;
    int t    = threadIdx.x & 63;
    int node = blockIdx.x * 4 + slot;

    __shared__ float s[4][QKVDIM];
    __shared__ float ss[4][64];

    const __half2* rp = (const __half2*)(qkv + (size_t)node * QKVDIM);
#pragma unroll
    for (int i = t; i < QKVDIM / 2; i += 64) {
        float2 f = __half22float2(rp[i]);
        s[slot][i * 2]     = f.x;
        s[slot][i * 2 + 1] = f.y;
    }
    __syncthreads();

    const float* sq = s[slot];
    const float* sk = s[slot] + EMBED;
    const float* sv = s[slot] + 2 * EMBED;

    int h = t >> 3, g = t & 7;
    float sc = 0.0f;
#pragma unroll
    for (int d = 0; d < HDIM; d++)
        sc = fmaf(sq[h * HDIM + d], sk[g * HDIM + d], sc);
    ss[slot][t] = sc * 0.125f;
    __syncthreads();

    if (t < 8) {
        float m = -1e30f;
#pragma unroll
        for (int gg = 0; gg < 8; gg++) m = fmaxf(m, ss[slot][t * 8 + gg]);
        float sum = 0.0f;
#pragma unroll
        for (int gg = 0; gg < 8; gg++) {
            float e = expf(ss[slot][t * 8 + gg] - m);
            ss[slot][t * 8 + gg] = e;
            sum += e;
        }
        float invs = 1.0f / sum;
#pragma unroll
        for (int gg = 0; gg < 8; gg++) ss[slot][t * 8 + gg] *= invs;
    }
    __syncthreads();

    __half* op = out + (size_t)node * EMBED;
#pragma unroll
    for (int j = 0; j < NHEADS; j++) {
        float o = 0.0f;
#pragma unroll
        for (int gg = 0; gg < 8; gg++)
            o = fmaf(ss[slot][j * 8 + gg], sv[gg * HDIM + t], o);
        op[j * HDIM + t] = __float2half(o);
    }
}

// ---------------- weight conversion -------------------------------------------
__global__ void __launch_bounds__(256) f2h_all_kernel(
    const float* __restrict__ Wq, const float* __restrict__ Wk,
    const float* __restrict__ Wv, const float* __restrict__ Wo,
    const float* __restrict__ W1, const float* __restrict__ W2,
    __half* __restrict__ wqkv, __half* __restrict__ wo,
    __half* __restrict__ w1, __half* __restrict__ w2)
{
    int y = blockIdx.y;
    const float* s; __half* d; int n4;
    if      (y == 0) { s = Wq; d = wqkv;                 n4 = EMBED*EMBED/4; }
    else if (y == 1) { s = Wk; d = wqkv + EMBED*EMBED;   n4 = EMBED*EMBED/4; }
    else if (y == 2) { s = Wv; d = wqkv + 2*EMBED*EMBED; n4 = EMBED*EMBED/4; }
    else if (y == 3) { s = Wo; d = wo;                   n4 = EMBED*EMBED/4; }
    else if (y == 4) { s = W1; d = w1;                   n4 = FFDIM*EMBED/4; }
    else             { s = W2; d = w2;                   n4 = FFDIM*EMBED/4; }
    for (int i = blockIdx.x * blockDim.x + threadIdx.x; i < n4; i += gridDim.x * blockDim.x) {
        float4 v = ((const float4*)s)[i];
        __half2* dp = (__half2*)d + i * 2;
        dp[0] = __floats2half2_rn(v.x, v.y);
        dp[1] = __floats2half2_rn(v.z, v.w);
    }
}

__global__ void __launch_bounds__(256) bias_cat_kernel(
    const float* __restrict__ bq, const float* __restrict__ bk,
    const float* __restrict__ bv, float* __restrict__ bqkv)
{
    int i = blockIdx.x * 256 + threadIdx.x;
    float val = (i < EMBED) ? bq[i] : (i < 2 * EMBED) ? bk[i - EMBED] : bv[i - 2 * EMBED];
    bqkv[i] = val;
}

// ---------------- host orchestration -----------------------------------------
extern "C" void kernel_launch(void* const* d_in, const int* in_sizes, int n_in,
                              void* d_out, int out_size)
{
    const float* x   = (const float*)d_in[0];
    const float* Wq  = (const float*)d_in[1];
    const float* bq  = (const float*)d_in[2];
    const float* Wk  = (const float*)d_in[3];
    const float* bk  = (const float*)d_in[4];
    const float* Wv  = (const float*)d_in[5];
    const float* bv  = (const float*)d_in[6];
    const float* Wo  = (const float*)d_in[7];
    const float* bo  = (const float*)d_in[8];
    const float* W1  = (const float*)d_in[9];
    const float* b1  = (const float*)d_in[10];
    const float* W2  = (const float*)d_in[11];
    const float* b2  = (const float*)d_in[12];
    const float* g1  = (const float*)d_in[13];
    const float* be1 = (const float*)d_in[14];
    const float* g2  = (const float*)d_in[15];
    const float* be2 = (const float*)d_in[16];
    float* out = (float*)d_out;

    __half *h, *qkv, *attnh, *ffh, *wqkv, *wo, *w1, *w2, *x1h;
    float *bqkv;
    cudaGetSymbolAddress((void**)&h,     g_h);
    cudaGetSymbolAddress((void**)&qkv,   g_qkv);
    cudaGetSymbolAddress((void**)&attnh, g_attnh);
    cudaGetSymbolAddress((void**)&x1h,   g_x1h);
    cudaGetSymbolAddress((void**)&ffh,   g_ffh);
    cudaGetSymbolAddress((void**)&wqkv,  g_wqkv);
    cudaGetSymbolAddress((void**)&wo,    g_wo);
    cudaGetSymbolAddress((void**)&w1,    g_w1);
    cudaGetSymbolAddress((void**)&w2,    g_w2);
    cudaGetSymbolAddress((void**)&bqkv,  g_bqkv);

    cudaFuncSetAttribute(gemm16_kernel<true,false,false,false,true>,
                         cudaFuncAttributeMaxDynamicSharedMemorySize, GSMEM);
    cudaFuncSetAttribute(gemm16_kernel<false,false,true,false,true>,
                         cudaFuncAttributeMaxDynamicSharedMemorySize, GSMEM);
    cudaFuncSetAttribute(gemm16_kernel<true,true,false,false,true>,
                         cudaFuncAttributeMaxDynamicSharedMemorySize, GSMEM);
    cudaFuncSetAttribute(gemm16_kernel<false,false,true,true,false>,
                         cudaFuncAttributeMaxDynamicSharedMemorySize, GSMEM);

    {
        dim3 g(256, 6);
        f2h_all_kernel<<<g, 256>>>(Wq, Wk, Wv, Wo, W1, W2, wqkv, wo, w1, w2);
        bias_cat_kernel<<<QKVDIM / 256, 256>>>(bq, bk, bv, bqkv);
    }

    // 1) h = LN1(x) -> fp16
    ln_kernel<<<N_NODES, 128>>>(x, g1, be1, h);

    // 2) qkv = h @ Wqkv^T + bqkv (fp16 out, fp16-chunk-acc)
    dim3 grdQKV(QKVDIM / BN, N_NODES / BM);   // (12, 512)
    gemm16_kernel<true,false,false,false,true><<<grdQKV, 256, GSMEM>>>(h, wqkv, bqkv, nullptr, qkv, EMBED, QKVDIM);

    // 3) per-node attention -> fp16
    attn_kernel<<<N_NODES / 4, 256>>>(qkv, attnh);

    // 4) x1h = x + attnh @ Wo^T + bo (fp16 out, fp32 residual in, f32 acc)
    dim3 grdE(EMBED / BN, N_NODES / BM);      // (4, 512)
    gemm16_kernel<false,false,true,false,true><<<grdE, 256, GSMEM>>>(attnh, wo, bo, x, x1h, EMBED, EMBED);

    // 5) h = LN2(x1h) -> fp16
    ln_h_kernel<<<N_NODES, 128>>>(x1h, g2, be2, h);

    // 6) ffh = relu(h @ W1^T + b1) -> fp16 (fp16-chunk-acc)
    dim3 grdF(FFDIM / BN, N_NODES / BM);      // (16, 512)
    gemm16_kernel<true,true,false,false,true><<<grdF, 256, GSMEM>>>(h, w1, b1, nullptr, ffh, EMBED, FFDIM);

    // 7) out = x1h + ffh @ W2^T + b2 (fp32 out, fp16 residual in, f32 acc)
    gemm16_kernel<false,false,true,true,false><<<grdE, 256, GSMEM>>>(ffh, w2, b2, x1h, out, FFDIM, EMBED);
}

// round 10
// speedup vs baseline: 1.0395x; 1.0395x over previous
#include <cuda_runtime.h>
#include <cuda_fp16.h>
#include <math.h>
#include <stdint.h>

#define N_NODES 65536
#define EMBED 512
#define FFDIM 2048
#define QKVDIM 1536
#define NHEADS 8
#define HDIM 64

// ---------------- scratch ----------------------------------------------------
__device__ __half g_h[(size_t)N_NODES * EMBED];
__device__ __half g_qkv[(size_t)N_NODES * QKVDIM];
__device__ __half g_attnh[(size_t)N_NODES * EMBED];
__device__ __half g_x1h[(size_t)N_NODES * EMBED];
__device__ __half g_ffh[(size_t)N_NODES * FFDIM];
__device__ __half g_wqkv[QKVDIM * EMBED];
__device__ float  g_bqkv[QKVDIM];
__device__ __half g_wo[EMBED * EMBED];
__device__ __half g_w1[FFDIM * EMBED];
__device__ __half g_w2[EMBED * FFDIM];

// ---------------- ptx helpers ------------------------------------------------
__device__ __forceinline__ uint32_t smem_u32(const void* p) {
    uint32_t a;
    asm("{ .reg .u64 t; cvta.to.shared.u64 t, %1; cvt.u32.u64 %0, t; }" : "=r"(a) : "l"(p));
    return a;
}
__device__ __forceinline__ void cp_async16(uint32_t saddr, const void* gaddr) {
    asm volatile("cp.async.cg.shared.global [%0], [%1], 16;\n" :: "r"(saddr), "l"(gaddr));
}
__device__ __forceinline__ void cpasync_mbar_arrive(uint32_t mbar) {
    asm volatile("cp.async.mbarrier.arrive.noinc.shared.b64 [%0];" :: "r"(mbar) : "memory");
}
__device__ __forceinline__ void mbar_init(uint32_t mbar, uint32_t cnt) {
    asm volatile("mbarrier.init.shared.b64 [%0], %1;" :: "r"(mbar), "r"(cnt) : "memory");
}
__device__ __forceinline__ void mbar_arrive(uint32_t mbar) {
    asm volatile("mbarrier.arrive.shared.b64 _, [%0];" :: "r"(mbar) : "memory");
}
__device__ __forceinline__ void mbar_wait(uint32_t mbar, uint32_t parity) {
    asm volatile(
        "{\n\t.reg .pred P;\n\t"
        "WL%=:\n\t"
        "mbarrier.try_wait.parity.acquire.cta.shared::cta.b64 P, [%0], %1, 0x989680;\n\t"
        "@P bra WD%=;\n\t"
        "bra WL%=;\n\t"
        "WD%=:\n\t}"
        :: "r"(mbar), "r"(parity) : "memory");
}
__device__ __forceinline__ void ldm_x4(uint32_t* r, uint32_t addr) {
    asm volatile("ldmatrix.sync.aligned.m8n8.x4.shared.b16 {%0,%1,%2,%3}, [%4];"
                 : "=r"(r[0]), "=r"(r[1]), "=r"(r[2]), "=r"(r[3]) : "r"(addr));
}
__device__ __forceinline__ void mma16816(float* d, const uint32_t* a, const uint32_t* b) {
    asm volatile(
        "mma.sync.aligned.m16n8k16.row.col.f32.f16.f16.f32 "
        "{%0,%1,%2,%3}, {%4,%5,%6,%7}, {%8,%9}, {%0,%1,%2,%3};"
        : "+f"(d[0]), "+f"(d[1]), "+f"(d[2]), "+f"(d[3])
        : "r"(a[0]), "r"(a[1]), "r"(a[2]), "r"(a[3]), "r"(b[0]), "r"(b[1]));
}

// ---------------- HMMA fp16 GEMM: C[N,M] = A[N,K] @ B[M,K]^T + epilogue -----
// CTA tile 128x256, BK=64, ROWB=144 (conflict-free ldmatrix). 512 threads =
// 16 warps (4 M-groups x 4 N-groups), warp tile 32x64 (identical per-warp
// code to the proven R8 config). 3-stage cp.async pipeline with mbarriers,
// no per-chunk __syncthreads. vs 128x128: half the cp.async SMEM-write
// traffic and half the B-tile L2 traffic per output element.
#define BM 128
#define BN 256
#define BK 64
#define ROWB 144
#define ATILEB (128 * ROWB)          // 18432
#define BTILEB (256 * ROWB)          // 36864
#define STAGEB (ATILEB + BTILEB)     // 55296 per stage
#define GSMEM (64 + 3 * STAGEB)      // 165952
#define GTHREADS 512

template<bool RELU, bool HASRES, bool RESHALF, bool OUTHALF>
__global__ void __launch_bounds__(GTHREADS) gemm16_kernel(
    const __half* __restrict__ A, const __half* __restrict__ B,
    const float* __restrict__ bias, const void* __restrict__ resv,
    void* __restrict__ Cv, int K, int M)
{
    extern __shared__ __align__(16) char smem[];
    const uint32_t sb = smem_u32(smem);
    const uint32_t tb = sb + 64;     // tiles base
    const int tid = threadIdx.x;
    const int lane = tid & 31;
    const int wid = tid >> 5;
    const int wm = wid & 3;          // 0..3, 32 rows each
    const int wn = wid >> 2;         // 0..3, 64 cols each
    const int bm = blockIdx.y * BM;
    const int bn = blockIdx.x * BN;

    if (tid == 0) {
#pragma unroll
        for (int s = 0; s < 3; s++) {
            mbar_init(sb + s * 8, GTHREADS);        // full[s]
            mbar_init(sb + 24 + s * 8, GTHREADS);   // free[s]
        }
    }
    __syncthreads();

    // cp.async slots: A tile 1024 segs (2/thread), B tile 2048 segs (4/thread)
    uint32_t a_soff[2]; const __half* agp[2];
#pragma unroll
    for (int i = 0; i < 2; i++) {
        int seg = tid + i * GTHREADS;
        int r = seg >> 3, c = seg & 7;
        a_soff[i] = r * ROWB + c * 16;
        agp[i] = A + (size_t)(bm + r) * K + c * 8;
    }
    uint32_t b_soff[4]; const __half* bgp[4];
#pragma unroll
    for (int i = 0; i < 4; i++) {
        int seg = tid + i * GTHREADS;
        int r = seg >> 3, c = seg & 7;
        b_soff[i] = r * ROWB + c * 16;
        bgp[i] = B + (size_t)(bn + r) * K + c * 8;
    }

    uint32_t a_off[2], b_off[4];
#pragma unroll
    for (int mf = 0; mf < 2; mf++)
        a_off[mf] = (wm * 32 + mf * 16 + (lane & 15)) * ROWB + ((lane >> 4) * 16);
#pragma unroll
    for (int p = 0; p < 4; p++)
        b_off[p] = (wn * 64 + p * 16 + ((lane >> 4) << 3) + (lane & 7)) * ROWB
                 + (((lane >> 3) & 1) * 16);

    float acc[2][8][4];
#pragma unroll
    for (int i = 0; i < 2; i++)
#pragma unroll
        for (int j = 0; j < 8; j++)
#pragma unroll
            for (int t = 0; t < 4; t++) acc[i][j][t] = 0.f;

    const int NC = K >> 6;

    // prologue: prefetch chunks 0 and 1 (stages 0, 1)
#pragma unroll
    for (int pc = 0; pc < 2; pc++) {
        const uint32_t base = tb + pc * STAGEB;
        const int ko = pc * BK;
#pragma unroll
        for (int i = 0; i < 2; i++) cp_async16(base + a_soff[i], agp[i] + ko);
#pragma unroll
        for (int i = 0; i < 4; i++) cp_async16(base + ATILEB + b_soff[i], bgp[i] + ko);
        cpasync_mbar_arrive(sb + pc * 8);   // full[pc]
    }

    int st = 0;            // compute stage
    uint32_t pful = 0;     // full-wait parity for compute
    int pt = 2;            // prefetch stage
    uint32_t wfree = 1;    // free-wait parity

#pragma unroll 1
    for (int chunk = 0; chunk < NC; chunk++) {
        // prefetch chunk+2 into stage pt
        const int pc = chunk + 2;
        if (pc < NC) {
            if (pc >= 3) mbar_wait(sb + 24 + pt * 8, wfree);
            const uint32_t base = tb + pt * STAGEB;
            const int ko = pc * BK;
#pragma unroll
            for (int i = 0; i < 2; i++) cp_async16(base + a_soff[i], agp[i] + ko);
#pragma unroll
            for (int i = 0; i < 4; i++) cp_async16(base + ATILEB + b_soff[i], bgp[i] + ko);
            cpasync_mbar_arrive(sb + pt * 8);
            if (pt == 2) { pt = 0; wfree ^= 1u; } else pt++;
        }

        // consume stage st
        mbar_wait(sb + st * 8, pful);
        const uint32_t ab = tb + st * STAGEB;
        const uint32_t bb = ab + ATILEB;
#pragma unroll
        for (int ks = 0; ks < 4; ks++) {
            uint32_t afr[2][4], bfr[4][4];
            ldm_x4(afr[0], ab + a_off[0] + ks * 32);
            ldm_x4(afr[1], ab + a_off[1] + ks * 32);
#pragma unroll
            for (int p = 0; p < 4; p++) ldm_x4(bfr[p], bb + b_off[p] + ks * 32);
#pragma unroll
            for (int mf = 0; mf < 2; mf++)
#pragma unroll
                for (int nf = 0; nf < 8; nf++)
                    mma16816(acc[mf][nf], afr[mf], &bfr[nf >> 1][(nf & 1) * 2]);
        }
        mbar_arrive(sb + 24 + st * 8);   // free[st]
        if (st == 2) { st = 0; pful ^= 1u; } else st++;
    }

    // epilogue
    const int mrow = bm + wm * 32 + (lane >> 2);
    const int ncol = bn + wn * 64 + (lane & 3) * 2;
#pragma unroll
    for (int mf = 0; mf < 2; mf++) {
#pragma unroll
        for (int half8 = 0; half8 < 2; half8++) {
            const int row = mrow + mf * 16 + half8 * 8;
#pragma unroll
            for (int nf = 0; nf < 8; nf++) {
                const int col = ncol + nf * 8;
                float c0 = acc[mf][nf][half8 * 2 + 0];
                float c1 = acc[mf][nf][half8 * 2 + 1];
                float2 b2 = *(const float2*)&bias[col];
                c0 += b2.x; c1 += b2.y;
                if (RELU) { c0 = fmaxf(c0, 0.f); c1 = fmaxf(c1, 0.f); }
                if (HASRES) {
                    if (RESHALF) {
                        __half2 r2 = *(const __half2*)((const __half*)resv + (size_t)row * M + col);
                        float2 rf = __half22float2(r2);
                        c0 += rf.x; c1 += rf.y;
                    } else {
                        float2 r2 = *(const float2*)((const float*)resv + (size_t)row * M + col);
                        c0 += r2.x; c1 += r2.y;
                    }
                }
                if (OUTHALF) {
                    *(__half2*)((__half*)Cv + (size_t)row * M + col) =
                        __floats2half2_rn(c0, c1);
                } else {
                    *(float2*)((float*)Cv + (size_t)row * M + col) =
                        make_float2(c0, c1);
                }
            }
        }
    }
}

// ---------------- LayerNorm (fp32 in) -> fp16 ---------------------------------
__global__ void __launch_bounds__(128) ln_kernel(
    const float* __restrict__ x, const float* __restrict__ gamma,
    const float* __restrict__ beta, __half* __restrict__ y)
{
    int row = blockIdx.x;
    int t = threadIdx.x;
    const float4* xp = (const float4*)(x + (size_t)row * EMBED);
    float4 v = xp[t];
    float s  = v.x + v.y + v.z + v.w;
    float s2 = v.x*v.x + v.y*v.y + v.z*v.z + v.w*v.w;
#pragma unroll
    for (int off = 16; off > 0; off >>= 1) {
        s  += __shfl_down_sync(0xffffffffu, s,  off);
        s2 += __shfl_down_sync(0xffffffffu, s2, off);
    }
    __shared__ float red[2][4];
    int warp = t >> 5, lane = t & 31;
    if (lane == 0) { red[0][warp] = s; red[1][warp] = s2; }
    __syncthreads();
    float tot  = red[0][0] + red[0][1] + red[0][2] + red[0][3];
    float tot2 = red[1][0] + red[1][1] + red[1][2] + red[1][3];
    float mu  = tot  * (1.0f / EMBED);
    float var = tot2 * (1.0f / EMBED) - mu * mu;
    float inv = rsqrtf(var + 1e-5f);
    float4 g4 = ((const float4*)gamma)[t];
    float4 b4 = ((const float4*)beta)[t];
    __half2* yp = (__half2*)(y + (size_t)row * EMBED) + t * 2;
    yp[0] = __floats2half2_rn((v.x - mu) * inv * g4.x + b4.x,
                              (v.y - mu) * inv * g4.y + b4.y);
    yp[1] = __floats2half2_rn((v.z - mu) * inv * g4.z + b4.z,
                              (v.w - mu) * inv * g4.w + b4.w);
}

// ---------------- LayerNorm (fp16 in) -> fp16 ---------------------------------
__global__ void __launch_bounds__(128) ln_h_kernel(
    const __half* __restrict__ x, const float* __restrict__ gamma,
    const float* __restrict__ beta, __half* __restrict__ y)
{
    int row = blockIdx.x;
    int t = threadIdx.x;
    uint2 raw = ((const uint2*)(x + (size_t)row * EMBED))[t];
    __half2 h0 = *reinterpret_cast<__half2*>(&raw.x);
    __half2 h1 = *reinterpret_cast<__half2*>(&raw.y);
    float2 f0 = __half22float2(h0);
    float2 f1 = __half22float2(h1);
    float s  = f0.x + f0.y + f1.x + f1.y;
    float s2 = f0.x*f0.x + f0.y*f0.y + f1.x*f1.x + f1.y*f1.y;
#pragma unroll
    for (int off = 16; off > 0; off >>= 1) {
        s  += __shfl_down_sync(0xffffffffu, s,  off);
        s2 += __shfl_down_sync(0xffffffffu, s2, off);
    }
    __shared__ float red[2][4];
    int warp = t >> 5, lane = t & 31;
    if (lane == 0) { red[0][warp] = s; red[1][warp] = s2; }
    __syncthreads();
    float tot  = red[0][0] + red[0][1] + red[0][2] + red[0][3];
    float tot2 = red[1][0] + red[1][1] + red[1][2] + red[1][3];
    float mu  = tot  * (1.0f / EMBED);
    float var = tot2 * (1.0f / EMBED) - mu * mu;
    float inv = rsqrtf(var + 1e-5f);
    float4 g4 = ((const float4*)gamma)[t];
    float4 b4 = ((const float4*)beta)[t];
    __half2* yp = (__half2*)(y + (size_t)row * EMBED) + t * 2;
    yp[0] = __floats2half2_rn((f0.x - mu) * inv * g4.x + b4.x,
                              (f0.y - mu) * inv * g4.y + b4.y);
    yp[1] = __floats2half2_rn((f1.x - mu) * inv * g4.z + b4.z,
                              (f1.y - mu) * inv * g4.w + b4.w);
}

// ---------------- per-node attention (8x8 heads), fp16 fused qkv -> fp16 -----
__global__ void __launch_bounds__(256) attn_kernel(
    const __half* __restrict__ qkv, __half* __restrict__ out)
{
    int slot = threadIdx.x >> 6;
    int t    = threadIdx.x & 63;
    int node = blockIdx.x * 4 + slot;

    __shared__ float s[4][QKVDIM];
    __shared__ float ss[4][64];

    const __half2* rp = (const __half2*)(qkv + (size_t)node * QKVDIM);
#pragma unroll
    for (int i = t; i < QKVDIM / 2; i += 64) {
        float2 f = __half22float2(rp[i]);
        s[slot][i * 2]     = f.x;
        s[slot][i * 2 + 1] = f.y;
    }
    __syncthreads();

    const float* sq = s[slot];
    const float* sk = s[slot] + EMBED;
    const float* sv = s[slot] + 2 * EMBED;

    int h = t >> 3, g = t & 7;
    float sc = 0.0f;
#pragma unroll
    for (int d = 0; d < HDIM; d++)
        sc = fmaf(sq[h * HDIM + d], sk[g * HDIM + d], sc);
    ss[slot][t] = sc * 0.125f;
    __syncthreads();

    if (t < 8) {
        float m = -1e30f;
#pragma unroll
        for (int gg = 0; gg < 8; gg++) m = fmaxf(m, ss[slot][t * 8 + gg]);
        float sum = 0.0f;
#pragma unroll
        for (int gg = 0; gg < 8; gg++) {
            float e = expf(ss[slot][t * 8 + gg] - m);
            ss[slot][t * 8 + gg] = e;
            sum += e;
        }
        float invs = 1.0f / sum;
#pragma unroll
        for (int gg = 0; gg < 8; gg++) ss[slot][t * 8 + gg] *= invs;
    }
    __syncthreads();

    __half* op = out + (size_t)node * EMBED;
#pragma unroll
    for (int j = 0; j < NHEADS; j++) {
        float o = 0.0f;
#pragma unroll
        for (int gg = 0; gg < 8; gg++)
            o = fmaf(ss[slot][j * 8 + gg], sv[gg * HDIM + t], o);
        op[j * HDIM + t] = __float2half(o);
    }
}

// ---------------- weight conversion -------------------------------------------
__global__ void __launch_bounds__(256) f2h_all_kernel(
    const float* __restrict__ Wq, const float* __restrict__ Wk,
    const float* __restrict__ Wv, const float* __restrict__ Wo,
    const float* __restrict__ W1, const float* __restrict__ W2,
    __half* __restrict__ wqkv, __half* __restrict__ wo,
    __half* __restrict__ w1, __half* __restrict__ w2)
{
    int y = blockIdx.y;
    const float* s; __half* d; int n4;
    if      (y == 0) { s = Wq; d = wqkv;                 n4 = EMBED*EMBED/4; }
    else if (y == 1) { s = Wk; d = wqkv + EMBED*EMBED;   n4 = EMBED*EMBED/4; }
    else if (y == 2) { s = Wv; d = wqkv + 2*EMBED*EMBED; n4 = EMBED*EMBED/4; }
    else if (y == 3) { s = Wo; d = wo;                   n4 = EMBED*EMBED/4; }
    else if (y == 4) { s = W1; d = w1;                   n4 = FFDIM*EMBED/4; }
    else             { s = W2; d = w2;                   n4 = FFDIM*EMBED/4; }
    for (int i = blockIdx.x * blockDim.x + threadIdx.x; i < n4; i += gridDim.x * blockDim.x) {
        float4 v = ((const float4*)s)[i];
        __half2* dp = (__half2*)d + i * 2;
        dp[0] = __floats2half2_rn(v.x, v.y);
        dp[1] = __floats2half2_rn(v.z, v.w);
    }
}

__global__ void __launch_bounds__(256) bias_cat_kernel(
    const float* __restrict__ bq, const float* __restrict__ bk,
    const float* __restrict__ bv, float* __restrict__ bqkv)
{
    int i = blockIdx.x * 256 + threadIdx.x;
    float val = (i < EMBED) ? bq[i] : (i < 2 * EMBED) ? bk[i - EMBED] : bv[i - 2 * EMBED];
    bqkv[i] = val;
}

// ---------------- host orchestration -----------------------------------------
extern "C" void kernel_launch(void* const* d_in, const int* in_sizes, int n_in,
                              void* d_out, int out_size)
{
    const float* x   = (const float*)d_in[0];
    const float* Wq  = (const float*)d_in[1];
    const float* bq  = (const float*)d_in[2];
    const float* Wk  = (const float*)d_in[3];
    const float* bk  = (const float*)d_in[4];
    const float* Wv  = (const float*)d_in[5];
    const float* bv  = (const float*)d_in[6];
    const float* Wo  = (const float*)d_in[7];
    const float* bo  = (const float*)d_in[8];
    const float* W1  = (const float*)d_in[9];
    const float* b1  = (const float*)d_in[10];
    const float* W2  = (const float*)d_in[11];
    const float* b2  = (const float*)d_in[12];
    const float* g1  = (const float*)d_in[13];
    const float* be1 = (const float*)d_in[14];
    const float* g2  = (const float*)d_in[15];
    const float* be2 = (const float*)d_in[16];
    float* out = (float*)d_out;

    __half *h, *qkv, *attnh, *ffh, *wqkv, *wo, *w1, *w2, *x1h;
    float *bqkv;
    cudaGetSymbolAddress((void**)&h,     g_h);
    cudaGetSymbolAddress((void**)&qkv,   g_qkv);
    cudaGetSymbolAddress((void**)&attnh, g_attnh);
    cudaGetSymbolAddress((void**)&x1h,   g_x1h);
    cudaGetSymbolAddress((void**)&ffh,   g_ffh);
    cudaGetSymbolAddress((void**)&wqkv,  g_wqkv);
    cudaGetSymbolAddress((void**)&wo,    g_wo);
    cudaGetSymbolAddress((void**)&w1,    g_w1);
    cudaGetSymbolAddress((void**)&w2,    g_w2);
    cudaGetSymbolAddress((void**)&bqkv,  g_bqkv);

    cudaFuncSetAttribute(gemm16_kernel<false,false,false,true>,
                         cudaFuncAttributeMaxDynamicSharedMemorySize, GSMEM);
    cudaFuncSetAttribute(gemm16_kernel<false,true,false,true>,
                         cudaFuncAttributeMaxDynamicSharedMemorySize, GSMEM);
    cudaFuncSetAttribute(gemm16_kernel<true,false,false,true>,
                         cudaFuncAttributeMaxDynamicSharedMemorySize, GSMEM);
    cudaFuncSetAttribute(gemm16_kernel<false,true,true,false>,
                         cudaFuncAttributeMaxDynamicSharedMemorySize, GSMEM);

    {
        dim3 g(256, 6);
        f2h_all_kernel<<<g, 256>>>(Wq, Wk, Wv, Wo, W1, W2, wqkv, wo, w1, w2);
        bias_cat_kernel<<<QKVDIM / 256, 256>>>(bq, bk, bv, bqkv);
    }

    // 1) h = LN1(x) -> fp16
    ln_kernel<<<N_NODES, 128>>>(x, g1, be1, h);

    // 2) qkv = h @ Wqkv^T + bqkv (fp16 out)
    dim3 grdQKV(QKVDIM / BN, N_NODES / BM);   // (6, 512)
    gemm16_kernel<false,false,false,true><<<grdQKV, GTHREADS, GSMEM>>>(h, wqkv, bqkv, nullptr, qkv, EMBED, QKVDIM);

    // 3) per-node attention -> fp16
    attn_kernel<<<N_NODES / 4, 256>>>(qkv, attnh);

    // 4) x1h = x + attnh @ Wo^T + bo (fp16 out, fp32 residual in)
    dim3 grdE(EMBED / BN, N_NODES / BM);      // (2, 512)
    gemm16_kernel<false,true,false,true><<<grdE, GTHREADS, GSMEM>>>(attnh, wo, bo, x, x1h, EMBED, EMBED);

    // 5) h = LN2(x1h) -> fp16
    ln_h_kernel<<<N_NODES, 128>>>(x1h, g2, be2, h);

    // 6) ffh = relu(h @ W1^T + b1) -> fp16
    dim3 grdF(FFDIM / BN, N_NODES / BM);      // (8, 512)
    gemm16_kernel<true,false,false,true><<<grdF, GTHREADS, GSMEM>>>(h, w1, b1, nullptr, ffh, EMBED, FFDIM);

    // 7) out = x1h + ffh @ W2^T + b2 (fp32 out, fp16 residual in)
    gemm16_kernel<false,true,true,false><<<grdE, GTHREADS, GSMEM>>>(ffh, w2, b2, x1h, out, FFDIM, EMBED);
}

// round 11
// speedup vs baseline: 1.2604x; 1.2125x over previous
#include <cuda_runtime.h>
#include <cuda_fp16.h>
#include <math.h>
#include <stdint.h>

#define N_NODES 65536
#define EMBED 512
#define FFDIM 2048
#define QKVDIM 1536
#define NHEADS 8
#define HDIM 64

// ---------------- scratch ----------------------------------------------------
__device__ __half g_h[(size_t)N_NODES * EMBED];
__device__ __half g_qkv[(size_t)N_NODES * QKVDIM];
__device__ __half g_attnh[(size_t)N_NODES * EMBED];
__device__ __half g_x1h[(size_t)N_NODES * EMBED];
__device__ __half g_ffh[(size_t)N_NODES * FFDIM];
__device__ __half g_wqkv[QKVDIM * EMBED];
__device__ float  g_bqkv[QKVDIM];
__device__ __half g_wo[EMBED * EMBED];
__device__ __half g_w1[FFDIM * EMBED];
__device__ __half g_w2[EMBED * FFDIM];

// ---------------- ptx helpers ------------------------------------------------
__device__ __forceinline__ uint32_t smem_u32(const void* p) {
    uint32_t a;
    asm("{ .reg .u64 t; cvta.to.shared.u64 t, %1; cvt.u32.u64 %0, t; }" : "=r"(a) : "l"(p));
    return a;
}
__device__ __forceinline__ void cp_async16(uint32_t saddr, const void* gaddr) {
    asm volatile("cp.async.cg.shared.global [%0], [%1], 16;\n" :: "r"(saddr), "l"(gaddr));
}
__device__ __forceinline__ void cpasync_mbar_arrive(uint32_t mbar) {
    asm volatile("cp.async.mbarrier.arrive.noinc.shared.b64 [%0];" :: "r"(mbar) : "memory");
}
__device__ __forceinline__ void mbar_init(uint32_t mbar, uint32_t cnt) {
    asm volatile("mbarrier.init.shared.b64 [%0], %1;" :: "r"(mbar), "r"(cnt) : "memory");
}
__device__ __forceinline__ void mbar_arrive(uint32_t mbar) {
    asm volatile("mbarrier.arrive.shared.b64 _, [%0];" :: "r"(mbar) : "memory");
}
__device__ __forceinline__ void mbar_wait(uint32_t mbar, uint32_t parity) {
    asm volatile(
        "{\n\t.reg .pred P;\n\t"
        "WL%=:\n\t"
        "mbarrier.try_wait.parity.acquire.cta.shared::cta.b64 P, [%0], %1, 0x989680;\n\t"
        "@P bra WD%=;\n\t"
        "bra WL%=;\n\t"
        "WD%=:\n\t}"
        :: "r"(mbar), "r"(parity) : "memory");
}
__device__ __forceinline__ void ldm_x4(uint32_t* r, uint32_t addr) {
    asm volatile("ldmatrix.sync.aligned.m8n8.x4.shared.b16 {%0,%1,%2,%3}, [%4];"
                 : "=r"(r[0]), "=r"(r[1]), "=r"(r[2]), "=r"(r[3]) : "r"(addr));
}
__device__ __forceinline__ void mma16816(float* d, const uint32_t* a, const uint32_t* b) {
    asm volatile(
        "mma.sync.aligned.m16n8k16.row.col.f32.f16.f16.f32 "
        "{%0,%1,%2,%3}, {%4,%5,%6,%7}, {%8,%9}, {%0,%1,%2,%3};"
        : "+f"(d[0]), "+f"(d[1]), "+f"(d[2]), "+f"(d[3])
        : "r"(a[0]), "r"(a[1]), "r"(a[2]), "r"(a[3]), "r"(b[0]), "r"(b[1]));
}

// ---------------- HMMA fp16 GEMM (R8 winner, unchanged) ----------------------
// CTA 128x128, BK=64 (ROWB=144 -> conflict-free ldmatrix), 3-stage cp.async
// pipeline with mbarriers (no per-chunk __syncthreads). 8 warps (4x2),
// warp tile 32x64.
#define BM 128
#define BN 128
#define BK 64
#define ROWB 144
#define TILEB (128 * ROWB)           // 18432 per tile (A or B)
#define STAGEB (2 * TILEB)           // 36864 per stage
#define GSMEM (64 + 3 * STAGEB)      // 110656

template<bool RELU, bool HASRES, bool RESHALF, bool OUTHALF>
__global__ void __launch_bounds__(256) gemm16_kernel(
    const __half* __restrict__ A, const __half* __restrict__ B,
    const float* __restrict__ bias, const void* __restrict__ resv,
    void* __restrict__ Cv, int K, int M)
{
    extern __shared__ __align__(16) char smem[];
    const uint32_t sb = smem_u32(smem);
    const uint32_t tb = sb + 64;
    const int tid = threadIdx.x;
    const int lane = tid & 31;
    const int wid = tid >> 5;
    const int wm = wid & 3;
    const int wn = wid >> 2;
    const int bm = blockIdx.y * BM;
    const int bn = blockIdx.x * BN;

    if (tid == 0) {
#pragma unroll
        for (int s = 0; s < 3; s++) {
            mbar_init(sb + s * 8, 256);
            mbar_init(sb + 24 + s * 8, 256);
        }
    }
    __syncthreads();

    uint32_t soff[4];
    const __half* agp[4];
    const __half* bgp[4];
#pragma unroll
    for (int i = 0; i < 4; i++) {
        int seg = tid + i * 256;
        int r = seg >> 3, c = seg & 7;
        soff[i] = r * ROWB + c * 16;
        agp[i] = A + (size_t)(bm + r) * K + c * 8;
        bgp[i] = B + (size_t)(bn + r) * K + c * 8;
    }

    uint32_t a_off[2], b_off[4];
#pragma unroll
    for (int mf = 0; mf < 2; mf++)
        a_off[mf] = (wm * 32 + mf * 16 + (lane & 15)) * ROWB + ((lane >> 4) * 16);
#pragma unroll
    for (int p = 0; p < 4; p++)
        b_off[p] = (wn * 64 + p * 16 + ((lane >> 4) << 3) + (lane & 7)) * ROWB
                 + (((lane >> 3) & 1) * 16);

    float acc[2][8][4];
#pragma unroll
    for (int i = 0; i < 2; i++)
#pragma unroll
        for (int j = 0; j < 8; j++)
#pragma unroll
            for (int t = 0; t < 4; t++) acc[i][j][t] = 0.f;

    const int NC = K >> 6;

#pragma unroll
    for (int pc = 0; pc < 2; pc++) {
        const uint32_t base = tb + pc * STAGEB;
        const int ko = pc * BK;
#pragma unroll
        for (int i = 0; i < 4; i++) {
            cp_async16(base + soff[i], agp[i] + ko);
            cp_async16(base + TILEB + soff[i], bgp[i] + ko);
        }
        cpasync_mbar_arrive(sb + pc * 8);
    }

    int st = 0;
    uint32_t pful = 0;
    int pt = 2;
    uint32_t wfree = 1;

#pragma unroll 1
    for (int chunk = 0; chunk < NC; chunk++) {
        const int pc = chunk + 2;
        if (pc < NC) {
            if (pc >= 3) mbar_wait(sb + 24 + pt * 8, wfree);
            const uint32_t base = tb + pt * STAGEB;
            const int ko = pc * BK;
#pragma unroll
            for (int i = 0; i < 4; i++) {
                cp_async16(base + soff[i], agp[i] + ko);
                cp_async16(base + TILEB + soff[i], bgp[i] + ko);
            }
            cpasync_mbar_arrive(sb + pt * 8);
            if (pt == 2) { pt = 0; wfree ^= 1u; } else pt++;
        }

        mbar_wait(sb + st * 8, pful);
        const uint32_t ab = tb + st * STAGEB;
        const uint32_t bb = ab + TILEB;
#pragma unroll
        for (int ks = 0; ks < 4; ks++) {
            uint32_t afr[2][4], bfr[4][4];
            ldm_x4(afr[0], ab + a_off[0] + ks * 32);
            ldm_x4(afr[1], ab + a_off[1] + ks * 32);
#pragma unroll
            for (int p = 0; p < 4; p++) ldm_x4(bfr[p], bb + b_off[p] + ks * 32);
#pragma unroll
            for (int mf = 0; mf < 2; mf++)
#pragma unroll
                for (int nf = 0; nf < 8; nf++)
                    mma16816(acc[mf][nf], afr[mf], &bfr[nf >> 1][(nf & 1) * 2]);
        }
        mbar_arrive(sb + 24 + st * 8);
        if (st == 2) { st = 0; pful ^= 1u; } else st++;
    }

    const int mrow = bm + wm * 32 + (lane >> 2);
    const int ncol = bn + wn * 64 + (lane & 3) * 2;
#pragma unroll
    for (int mf = 0; mf < 2; mf++) {
#pragma unroll
        for (int half8 = 0; half8 < 2; half8++) {
            const int row = mrow + mf * 16 + half8 * 8;
#pragma unroll
            for (int nf = 0; nf < 8; nf++) {
                const int col = ncol + nf * 8;
                float c0 = acc[mf][nf][half8 * 2 + 0];
                float c1 = acc[mf][nf][half8 * 2 + 1];
                float2 b2 = *(const float2*)&bias[col];
                c0 += b2.x; c1 += b2.y;
                if (RELU) { c0 = fmaxf(c0, 0.f); c1 = fmaxf(c1, 0.f); }
                if (HASRES) {
                    if (RESHALF) {
                        __half2 r2 = *(const __half2*)((const __half*)resv + (size_t)row * M + col);
                        float2 rf = __half22float2(r2);
                        c0 += rf.x; c1 += rf.y;
                    } else {
                        float2 r2 = *(const float2*)((const float*)resv + (size_t)row * M + col);
                        c0 += r2.x; c1 += r2.y;
                    }
                }
                if (OUTHALF) {
                    *(__half2*)((__half*)Cv + (size_t)row * M + col) =
                        __floats2half2_rn(c0, c1);
                } else {
                    *(float2*)((float*)Cv + (size_t)row * M + col) =
                        make_float2(c0, c1);
                }
            }
        }
    }
}

// ---------------- LayerNorm (fp32 in) -> fp16, warp-per-row -------------------
__global__ void __launch_bounds__(256) ln_kernel(
    const float* __restrict__ x, const float* __restrict__ gamma,
    const float* __restrict__ beta, __half* __restrict__ y)
{
    const int w = threadIdx.x >> 5, lane = threadIdx.x & 31;
    const size_t row = (size_t)blockIdx.x * 8 + w;
    const float4* xp = (const float4*)(x + row * EMBED);
    float4 v[4];
    float s = 0.f, s2 = 0.f;
#pragma unroll
    for (int k = 0; k < 4; k++) {
        v[k] = xp[k * 32 + lane];
        s  += v[k].x + v[k].y + v[k].z + v[k].w;
        s2 += v[k].x*v[k].x + v[k].y*v[k].y + v[k].z*v[k].z + v[k].w*v[k].w;
    }
#pragma unroll
    for (int o = 16; o > 0; o >>= 1) {
        s  += __shfl_xor_sync(0xffffffffu, s,  o);
        s2 += __shfl_xor_sync(0xffffffffu, s2, o);
    }
    const float mu = s * (1.0f / EMBED);
    const float inv = rsqrtf(s2 * (1.0f / EMBED) - mu * mu + 1e-5f);
    __half2* yp = (__half2*)(y + row * EMBED);
#pragma unroll
    for (int k = 0; k < 4; k++) {
        float4 g4 = ((const float4*)gamma)[k * 32 + lane];
        float4 b4 = ((const float4*)beta)[k * 32 + lane];
        yp[(k * 32 + lane) * 2] =
            __floats2half2_rn((v[k].x - mu) * inv * g4.x + b4.x,
                              (v[k].y - mu) * inv * g4.y + b4.y);
        yp[(k * 32 + lane) * 2 + 1] =
            __floats2half2_rn((v[k].z - mu) * inv * g4.z + b4.z,
                              (v[k].w - mu) * inv * g4.w + b4.w);
    }
}

// ---------------- LayerNorm (fp16 in) -> fp16, warp-per-row -------------------
__global__ void __launch_bounds__(256) ln_h_kernel(
    const __half* __restrict__ x, const float* __restrict__ gamma,
    const float* __restrict__ beta, __half* __restrict__ y)
{
    const int w = threadIdx.x >> 5, lane = threadIdx.x & 31;
    const size_t row = (size_t)blockIdx.x * 8 + w;
    const uint4* xp = (const uint4*)(x + row * EMBED);   // 64 uint4 per row
    uint4 raw[2];
    float f[16];
    float s = 0.f, s2 = 0.f;
#pragma unroll
    for (int k = 0; k < 2; k++) {
        raw[k] = xp[k * 32 + lane];
        const __half2* hp = (const __half2*)&raw[k];
#pragma unroll
        for (int j = 0; j < 4; j++) {
            float2 fj = __half22float2(hp[j]);
            f[k * 8 + j * 2]     = fj.x;
            f[k * 8 + j * 2 + 1] = fj.y;
            s  += fj.x + fj.y;
            s2 += fj.x * fj.x + fj.y * fj.y;
        }
    }
#pragma unroll
    for (int o = 16; o > 0; o >>= 1) {
        s  += __shfl_xor_sync(0xffffffffu, s,  o);
        s2 += __shfl_xor_sync(0xffffffffu, s2, o);
    }
    const float mu = s * (1.0f / EMBED);
    const float inv = rsqrtf(s2 * (1.0f / EMBED) - mu * mu + 1e-5f);
    __half2* yp = (__half2*)(y + row * EMBED);
#pragma unroll
    for (int k = 0; k < 2; k++) {
        // this uint4 covers halfs [ (k*32+lane)*8 , +8 ) = float4-pairs
        const int base4 = (k * 32 + lane) * 2;   // float4 index
#pragma unroll
        for (int q = 0; q < 2; q++) {
            float4 g4 = ((const float4*)gamma)[base4 + q];
            float4 b4 = ((const float4*)beta)[base4 + q];
            yp[(base4 + q) * 2] =
                __floats2half2_rn((f[k*8 + q*4 + 0] - mu) * inv * g4.x + b4.x,
                                  (f[k*8 + q*4 + 1] - mu) * inv * g4.y + b4.y);
            yp[(base4 + q) * 2 + 1] =
                __floats2half2_rn((f[k*8 + q*4 + 2] - mu) * inv * g4.z + b4.z,
                                  (f[k*8 + q*4 + 3] - mu) * inv * g4.w + b4.w);
        }
    }
}

// ---------------- per-node attention, warp-per-node ---------------------------
// 8 warps/block = 8 nodes, warp-sync only (no __syncthreads in the hot path).
__global__ void __launch_bounds__(256) attn_kernel(
    const __half* __restrict__ qkv, __half* __restrict__ out)
{
    const int w = threadIdx.x >> 5, lane = threadIdx.x & 31;
    const size_t node = (size_t)blockIdx.x * 8 + w;

    __shared__ __half s[8][QKVDIM];   // 24 KB
    __shared__ float sa[8][64];       // 2 KB

    // load q|k|v row: 1536 halfs = 192 uint4, 6 per lane
    const uint4* rp = (const uint4*)(qkv + node * QKVDIM);
    uint4* sp = (uint4*)s[w];
#pragma unroll
    for (int i = 0; i < 6; i++) sp[i * 32 + lane] = rp[i * 32 + lane];
    __syncwarp();

    const __half* sq = s[w];
    const __half* sk = s[w] + EMBED;
    const __half* sv = s[w] + 2 * EMBED;

    // scores: pair p = lane + pi*32; h = p>>3, g = p&7
    float sc[2];
#pragma unroll
    for (int pi = 0; pi < 2; pi++) {
        const int p = lane + pi * 32;
        const int h = p >> 3, g = p & 7;
        const __half2* qh = (const __half2*)(sq + h * HDIM);
        const __half2* kh = (const __half2*)(sk + g * HDIM);
        float a = 0.f;
#pragma unroll
        for (int dd = 0; dd < 32; dd++) {
            const int d = (dd + g * 4 + (h & 3) * 8) & 31;  // bank rotation
            float2 a2 = __half22float2(qh[d]);
            float2 b2 = __half22float2(kh[d]);
            a += a2.x * b2.x + a2.y * b2.y;
        }
        sc[pi] = a * 0.125f;
    }

    // softmax over 8-lane groups (same h per group)
#pragma unroll
    for (int pi = 0; pi < 2; pi++) {
        float m = sc[pi];
#pragma unroll
        for (int o = 4; o > 0; o >>= 1)
            m = fmaxf(m, __shfl_xor_sync(0xffffffffu, m, o));
        float e = expf(sc[pi] - m);
        float ssum = e;
#pragma unroll
        for (int o = 4; o > 0; o >>= 1)
            ssum += __shfl_xor_sync(0xffffffffu, ssum, o);
        sa[w][lane + pi * 32] = e / ssum;
    }
    __syncwarp();

    // out[h*64+d] = sum_g a[h][g] * v[g*64+d]; lane covers d = lane, lane+32
    __half* op = out + node * EMBED;
#pragma unroll
    for (int h = 0; h < NHEADS; h++) {
        float o0 = 0.f, o1 = 0.f;
#pragma unroll
        for (int g = 0; g < 8; g++) {
            const float a = sa[w][h * 8 + g];
            o0 += a * __half2float(sv[g * HDIM + lane]);
            o1 += a * __half2float(sv[g * HDIM + 32 + lane]);
        }
        op[h * HDIM + lane]      = __float2half(o0);
        op[h * HDIM + 32 + lane] = __float2half(o1);
    }
}

// ---------------- weight conversion -------------------------------------------
__global__ void __launch_bounds__(256) f2h_all_kernel(
    const float* __restrict__ Wq, const float* __restrict__ Wk,
    const float* __restrict__ Wv, const float* __restrict__ Wo,
    const float* __restrict__ W1, const float* __restrict__ W2,
    __half* __restrict__ wqkv, __half* __restrict__ wo,
    __half* __restrict__ w1, __half* __restrict__ w2)
{
    int y = blockIdx.y;
    const float* s; __half* d; int n4;
    if      (y == 0) { s = Wq; d = wqkv;                 n4 = EMBED*EMBED/4; }
    else if (y == 1) { s = Wk; d = wqkv + EMBED*EMBED;   n4 = EMBED*EMBED/4; }
    else if (y == 2) { s = Wv; d = wqkv + 2*EMBED*EMBED; n4 = EMBED*EMBED/4; }
    else if (y == 3) { s = Wo; d = wo;                   n4 = EMBED*EMBED/4; }
    else if (y == 4) { s = W1; d = w1;                   n4 = FFDIM*EMBED/4; }
    else             { s = W2; d = w2;                   n4 = FFDIM*EMBED/4; }
    for (int i = blockIdx.x * blockDim.x + threadIdx.x; i < n4; i += gridDim.x * blockDim.x) {
        float4 v = ((const float4*)s)[i];
        __half2* dp = (__half2*)d + i * 2;
        dp[0] = __floats2half2_rn(v.x, v.y);
        dp[1] = __floats2half2_rn(v.z, v.w);
    }
}

__global__ void __launch_bounds__(256) bias_cat_kernel(
    const float* __restrict__ bq, const float* __restrict__ bk,
    const float* __restrict__ bv, float* __restrict__ bqkv)
{
    int i = blockIdx.x * 256 + threadIdx.x;
    float val = (i < EMBED) ? bq[i] : (i < 2 * EMBED) ? bk[i - EMBED] : bv[i - 2 * EMBED];
    bqkv[i] = val;
}

// ---------------- host orchestration -----------------------------------------
extern "C" void kernel_launch(void* const* d_in, const int* in_sizes, int n_in,
                              void* d_out, int out_size)
{
    const float* x   = (const float*)d_in[0];
    const float* Wq  = (const float*)d_in[1];
    const float* bq  = (const float*)d_in[2];
    const float* Wk  = (const float*)d_in[3];
    const float* bk  = (const float*)d_in[4];
    const float* Wv  = (const float*)d_in[5];
    const float* bv  = (const float*)d_in[6];
    const float* Wo  = (const float*)d_in[7];
    const float* bo  = (const float*)d_in[8];
    const float* W1  = (const float*)d_in[9];
    const float* b1  = (const float*)d_in[10];
    const float* W2  = (const float*)d_in[11];
    const float* b2  = (const float*)d_in[12];
    const float* g1  = (const float*)d_in[13];
    const float* be1 = (const float*)d_in[14];
    const float* g2  = (const float*)d_in[15];
    const float* be2 = (const float*)d_in[16];
    float* out = (float*)d_out;

    __half *h, *qkv, *attnh, *ffh, *wqkv, *wo, *w1, *w2, *x1h;
    float *bqkv;
    cudaGetSymbolAddress((void**)&h,     g_h);
    cudaGetSymbolAddress((void**)&qkv,   g_qkv);
    cudaGetSymbolAddress((void**)&attnh, g_attnh);
    cudaGetSymbolAddress((void**)&x1h,   g_x1h);
    cudaGetSymbolAddress((void**)&ffh,   g_ffh);
    cudaGetSymbolAddress((void**)&wqkv,  g_wqkv);
    cudaGetSymbolAddress((void**)&wo,    g_wo);
    cudaGetSymbolAddress((void**)&w1,    g_w1);
    cudaGetSymbolAddress((void**)&w2,    g_w2);
    cudaGetSymbolAddress((void**)&bqkv,  g_bqkv);

    cudaFuncSetAttribute(gemm16_kernel<false,false,false,true>,
                         cudaFuncAttributeMaxDynamicSharedMemorySize, GSMEM);
    cudaFuncSetAttribute(gemm16_kernel<false,true,false,true>,
                         cudaFuncAttributeMaxDynamicSharedMemorySize, GSMEM);
    cudaFuncSetAttribute(gemm16_kernel<true,false,false,true>,
                         cudaFuncAttributeMaxDynamicSharedMemorySize, GSMEM);
    cudaFuncSetAttribute(gemm16_kernel<false,true,true,false>,
                         cudaFuncAttributeMaxDynamicSharedMemorySize, GSMEM);

    {
        dim3 g(256, 6);
        f2h_all_kernel<<<g, 256>>>(Wq, Wk, Wv, Wo, W1, W2, wqkv, wo, w1, w2);
        bias_cat_kernel<<<QKVDIM / 256, 256>>>(bq, bk, bv, bqkv);
    }

    // 1) h = LN1(x) -> fp16
    ln_kernel<<<N_NODES / 8, 256>>>(x, g1, be1, h);

    // 2) qkv = h @ Wqkv^T + bqkv (fp16 out)
    dim3 grdQKV(QKVDIM / BN, N_NODES / BM);   // (12, 512)
    gemm16_kernel<false,false,false,true><<<grdQKV, 256, GSMEM>>>(h, wqkv, bqkv, nullptr, qkv, EMBED, QKVDIM);

    // 3) per-node attention -> fp16
    attn_kernel<<<N_NODES / 8, 256>>>(qkv, attnh);

    // 4) x1h = x + attnh @ Wo^T + bo (fp16 out, fp32 residual in)
    dim3 grdE(EMBED / BN, N_NODES / BM);      // (4, 512)
    gemm16_kernel<false,true,false,true><<<grdE, 256, GSMEM>>>(attnh, wo, bo, x, x1h, EMBED, EMBED);

    // 5) h = LN2(x1h) -> fp16
    ln_h_kernel<<<N_NODES / 8, 256>>>(x1h, g2, be2, h);

    // 6) ffh = relu(h @ W1^T + b1) -> fp16
    dim3 grdF(FFDIM / BN, N_NODES / BM);      // (16, 512)
    gemm16_kernel<true,false,false,true><<<grdF, 256, GSMEM>>>(h, w1, b1, nullptr, ffh, EMBED, FFDIM);

    // 7) out = x1h + ffh @ W2^T + b2 (fp32 out, fp16 residual in)
    gemm16_kernel<false,true,true,false><<<grdE, 256, GSMEM>>>(ffh, w2, b2, x1h, out, FFDIM, EMBED);
}